// round 1
// baseline (speedup 1.0000x reference)
#include <cuda_runtime.h>
#include <math.h>

// Problem constants (fixed shapes)
#define KDICT 512
#define DIMZ  256
#define NROWS 32768          // bs*W*H = 32*32*32
#define BSZ   32

// smem layout (floats)
//  sZ   : [256][32]            8192
//  sCB  : [512][65]           33280   (GEMM1 stage; reused as L/E and GEMM2 stage)
//  sProb: [512]                 512
//  sZi2 : [32]                   32
//  sRed : [16]                   16
#define SM_F  (8192 + 33280 + 512 + 32 + 16)
#define SM_BYTES (SM_F * 4)

__device__ float g_cbn[KDICT * DIMZ];
__device__ float g_avg[KDICT];
__device__ float g_kldd;
__device__ float g_kldc;

// ---------------------------------------------------------------- zero accums
__global__ void k_zero() {
    int t = threadIdx.x;
    if (t < KDICT) g_avg[t] = 0.0f;
    if (t == 0) { g_kldd = 0.0f; g_kldc = 0.0f; }
}

// ------------------------------------------------- L2-normalize codebook rows
__global__ void k_norm(const float* __restrict__ cb) {
    int row = blockIdx.x;      // 512 blocks
    int t = threadIdx.x;       // 256 threads
    float c = cb[row * DIMZ + t];
    float s = c * c;
    #pragma unroll
    for (int o = 16; o; o >>= 1) s += __shfl_xor_sync(0xffffffffu, s, o);
    __shared__ float ws[8];
    if ((t & 31) == 0) ws[t >> 5] = s;
    __syncthreads();
    float tot = 0.0f;
    #pragma unroll
    for (int i = 0; i < 8; i++) tot += ws[i];
    g_cbn[row * DIMZ + t] = c * (1.0f / sqrtf(tot));
}

// --------------------------------------------------------------- fused main
// One block = 32 rows (fixed b,w ; h = 0..31). 256 threads. 1024 blocks.
__global__ __launch_bounds__(256, 1)
void k_main(const float* __restrict__ z, const float* __restrict__ kappa,
            const float* __restrict__ gu, float* __restrict__ out) {
    extern __shared__ float sm[];
    float* sZ    = sm;                    // [d][32]
    float* sCB   = sm + 8192;             // [k][65] during GEMM1
    float* L     = sm + 8192;             // [32][512] logits / t2 / GEMM2 stage
    float* E     = sm + 8192 + 16384;     // [32][512] e / encodings
    float* sProb = sm + 8192 + 33280;     // [512]
    float* sZi2  = sProb + 512;           // [32]
    float* sRed  = sZi2 + 32;             // [16]

    const int t    = threadIdx.x;
    const int lane = t & 31;
    const int w8   = t >> 5;
    const int blk  = blockIdx.x;
    const int b    = blk >> 5;
    const int w    = blk & 31;
    const int R0   = blk << 5;

    const float* zb = z + (size_t)b * 262144 + w * 32;   // + d*1024 + h

    // ---- phase 0: load z tile (coalesced), zero sProb
    #pragma unroll
    for (int dd = 0; dd < 32; dd++) {
        int d = (w8 << 5) + dd;
        sZ[d * 32 + lane] = zb[d * 1024 + lane];
    }
    sProb[t] = 0.0f;
    sProb[t + 256] = 0.0f;

    const float kq = fminf(fmaxf(kappa[0], 1e-5f), 1e5f);

    // ---- GEMM1: logits[32][512] = z_tile @ cbn^T
    const int tr = t >> 6;        // 0..3  -> rows tr*8 .. tr*8+7
    const int tk = t & 63;        // 0..63 -> k = tk + 64*j
    float acc[8][8];
    #pragma unroll
    for (int i = 0; i < 8; i++)
        #pragma unroll
        for (int j = 0; j < 8; j++) acc[i][j] = 0.0f;

    for (int dt = 0; dt < 256; dt += 64) {
        __syncthreads();
        // stage cbn[:, dt:dt+64] into sCB[k][65]
        #pragma unroll
        for (int i = 0; i < 32; i++) {
            int f = t + (i << 8);           // 0..8191
            int k = f >> 4, d4 = f & 15;
            const float4 v = *(const float4*)(g_cbn + k * DIMZ + dt + (d4 << 2));
            float* dst = sCB + k * 65 + (d4 << 2);
            dst[0] = v.x; dst[1] = v.y; dst[2] = v.z; dst[3] = v.w;
        }
        __syncthreads();
        #pragma unroll 4
        for (int dd = 0; dd < 64; dd++) {
            float zf[8];
            float4 z0 = *(float4*)(sZ + (dt + dd) * 32 + (tr << 3));
            float4 z1 = *(float4*)(sZ + (dt + dd) * 32 + (tr << 3) + 4);
            zf[0] = z0.x; zf[1] = z0.y; zf[2] = z0.z; zf[3] = z0.w;
            zf[4] = z1.x; zf[5] = z1.y; zf[6] = z1.z; zf[7] = z1.w;
            float cf[8];
            #pragma unroll
            for (int j = 0; j < 8; j++) cf[j] = sCB[(tk + (j << 6)) * 65 + dd];
            #pragma unroll
            for (int i = 0; i < 8; i++)
                #pragma unroll
                for (int j = 0; j < 8; j++)
                    acc[i][j] = fmaf(zf[i], cf[j], acc[i][j]);
        }
    }
    __syncthreads();
    #pragma unroll
    for (int i = 0; i < 8; i++)
        #pragma unroll
        for (int j = 0; j < 8; j++)
            L[((tr << 3) + i) * KDICT + tk + (j << 6)] = acc[i][j] * kq;
    __syncthreads();

    // ---- softmax + gumbel: warp w8 owns rows w8*4 .. +3
    float kd_part = 0.0f;
    float probloc[16];
    #pragma unroll
    for (int q = 0; q < 16; q++) probloc[q] = 0.0f;

    for (int rr = 0; rr < 4; rr++) {
        const int r = (w8 << 2) + rr;
        float* Lr = L + r * KDICT;
        float* Er = E + r * KDICT;
        const float* gr = gu + (size_t)(R0 + r) * KDICT;

        float m = -1e30f;
        #pragma unroll
        for (int q = 0; q < 16; q++) m = fmaxf(m, Lr[lane + (q << 5)]);
        #pragma unroll
        for (int o = 16; o; o >>= 1) m = fmaxf(m, __shfl_xor_sync(0xffffffffu, m, o));

        float Zs = 0.0f, Ss = 0.0f, m2 = -1e30f;
        #pragma unroll
        for (int q = 0; q < 16; q++) {
            int k = lane + (q << 5);
            float lc = fmaxf(Lr[k] - m, -50.0f);      // upper clip never active
            float e = __expf(lc);
            Zs += e; Ss += e * lc;
            float u = gr[k];
            float g = -__logf(1e-10f - __logf(u + 1e-10f));
            float t2 = (lc + g) * 2.0f;               // /TEMPERATURE
            Er[k] = e;
            Lr[k] = t2;
            m2 = fmaxf(m2, t2);
        }
        #pragma unroll
        for (int o = 16; o; o >>= 1) {
            Zs += __shfl_xor_sync(0xffffffffu, Zs, o);
            Ss += __shfl_xor_sync(0xffffffffu, Ss, o);
            m2 = fmaxf(m2, __shfl_xor_sync(0xffffffffu, m2, o));
        }
        float zi = 1.0f / Zs;
        if (lane == 0) kd_part += Ss * zi - __logf(Zs);   // sum p*logp for row

        float Z2 = 0.0f;
        #pragma unroll
        for (int q = 0; q < 16; q++) {
            int k = lane + (q << 5);
            probloc[q] += Er[k] * zi;                 // probabilities accum
            float eg = __expf(Lr[k] - m2);
            Z2 += eg;
            Er[k] = eg;                               // unnormalized encodings
        }
        #pragma unroll
        for (int o = 16; o; o >>= 1) Z2 += __shfl_xor_sync(0xffffffffu, Z2, o);
        if (lane == 0) sZi2[r] = 1.0f / Z2;
    }
    #pragma unroll
    for (int q = 0; q < 16; q++) atomicAdd(sProb + lane + (q << 5), probloc[q]);
    __syncthreads();
    atomicAdd(g_avg + t, sProb[t]);
    atomicAdd(g_avg + t + 256, sProb[t + 256]);

    // ---- GEMM2: zq[32][256] = enc @ cbn    (enc = E * (1/Z2), folded at end)
    float acc2[8][4];
    #pragma unroll
    for (int i = 0; i < 8; i++)
        #pragma unroll
        for (int jj = 0; jj < 4; jj++) acc2[i][jj] = 0.0f;

    for (int kt = 0; kt < 512; kt += 64) {
        __syncthreads();
        // stage cbn[kt:kt+64][0:256] into L region [kk][256]
        #pragma unroll
        for (int i = 0; i < 16; i++) {
            int f = t + (i << 8);            // 0..4095
            int kk = f >> 6, c4 = f & 63;
            *(float4*)(L + kk * 256 + (c4 << 2)) =
                *(const float4*)(g_cbn + (size_t)(kt + kk) * DIMZ + (c4 << 2));
        }
        __syncthreads();
        #pragma unroll 4
        for (int kk = 0; kk < 64; kk++) {
            float ef[8];
            #pragma unroll
            for (int i = 0; i < 8; i++)
                ef[i] = E[((tr << 3) + i) * KDICT + kt + kk];   // broadcast
            float cf2[4];
            #pragma unroll
            for (int jj = 0; jj < 4; jj++) cf2[jj] = L[kk * 256 + tk + (jj << 6)];
            #pragma unroll
            for (int i = 0; i < 8; i++)
                #pragma unroll
                for (int jj = 0; jj < 4; jj++)
                    acc2[i][jj] = fmaf(ef[i], cf2[jj], acc2[i][jj]);
        }
    }

    // ---- epilogue: scale by 1/Z2, write z_to_decoder, kld_continuous partial
    float kldc_part = 0.0f;
    float zinv[8];
    #pragma unroll
    for (int i = 0; i < 8; i++) zinv[i] = sZi2[(tr << 3) + i];

    #pragma unroll
    for (int jj = 0; jj < 4; jj++) {
        int d = tk + (jj << 6);
        const float* zp = zb + d * 1024 + (tr << 3);
        float4 zv0 = *(const float4*)zp;
        float4 zv1 = *(const float4*)(zp + 4);
        float zr[8] = {zv0.x, zv0.y, zv0.z, zv0.w, zv1.x, zv1.y, zv1.z, zv1.w};
        float v[8];
        #pragma unroll
        for (int i = 0; i < 8; i++) {
            float zq = acc2[i][jj] * zinv[i];
            v[i] = zq;
            kldc_part += zr[i] * (zr[i] - zq);
        }
        float* op = out + (size_t)b * 262144 + ((size_t)d << 10) + w * 32 + (tr << 3);
        *(float4*)op       = make_float4(v[0], v[1], v[2], v[3]);
        *(float4*)(op + 4) = make_float4(v[4], v[5], v[6], v[7]);
    }

    // ---- block reduce kldc / kldd, single atomic each
    float vc = kldc_part, vk = kd_part;
    #pragma unroll
    for (int o = 16; o; o >>= 1) {
        vc += __shfl_xor_sync(0xffffffffu, vc, o);
        vk += __shfl_xor_sync(0xffffffffu, vk, o);
    }
    if (lane == 0) { sRed[w8] = vc; sRed[8 + w8] = vk; }
    __syncthreads();
    if (t == 0) {
        float sc = 0.0f, sk = 0.0f;
        #pragma unroll
        for (int i = 0; i < 8; i++) { sc += sRed[i]; sk += sRed[8 + i]; }
        atomicAdd(&g_kldc, sc);
        atomicAdd(&g_kldd, sk);
    }
}

// ----------------------------------------------------------------- finalize
__global__ void k_fin(const float* __restrict__ kappa, float* __restrict__ out,
                      int out_size) {
    int t = threadIdx.x;  // 512
    float a = g_avg[t] * (1.0f / (float)NROWS);
    a = fmaxf(a, 1e-10f);
    float term = a * logf(a + 1e-10f);
    #pragma unroll
    for (int o = 16; o; o >>= 1) term += __shfl_xor_sync(0xffffffffu, term, o);
    __shared__ float ws[16];
    if ((t & 31) == 0) ws[t >> 5] = term;
    __syncthreads();
    if (t == 0) {
        float s = 0.0f;
        #pragma unroll
        for (int i = 0; i < 16; i++) s += ws[i];
        float kq = fminf(fmaxf(kappa[0], 1e-5f), 1e5f);
        float loss = (g_kldd + g_kldc * kq) * (1.0f / (float)BSZ);
        if (out_size >= 8388609) out[8388608] = loss;
        if (out_size >= 8388610) out[8388609] = expf(-s);
    }
}

// ------------------------------------------------------------------ launcher
extern "C" void kernel_launch(void* const* d_in, const int* in_sizes, int n_in,
                              void* d_out, int out_size) {
    const float* z     = (const float*)d_in[0];
    const float* kappa = (const float*)d_in[1];
    const float* cb    = (const float*)d_in[2];
    const float* gu    = (const float*)d_in[3];
    float* out = (float*)d_out;

    cudaFuncSetAttribute(k_main, cudaFuncAttributeMaxDynamicSharedMemorySize,
                         SM_BYTES);
    k_zero<<<1, 512>>>();
    k_norm<<<512, 256>>>(cb);
    k_main<<<1024, 256, SM_BYTES>>>(z, kappa, gu, out);
    k_fin<<<1, 512>>>(kappa, out, out_size);
}

// round 2
// speedup vs baseline: 1.0003x; 1.0003x over previous
#include <cuda_runtime.h>
#include <math.h>

// Problem constants (fixed shapes)
#define KDICT 512
#define DIMZ  256
#define NROWS 32768          // bs*W*H = 32*32*32
#define BSZ   32

// smem layout (floats)
//  sZ   : [256][32]            8192
//  sCB  : [512][65]           33280   (GEMM1 stage; reused as L/E and GEMM2 stage)
//  sProb: [512]                 512
//  sZi2 : [32]                   32
//  sRed : [16]                   16
#define SM_F  (8192 + 33280 + 512 + 32 + 16)
#define SM_BYTES (SM_F * 4)

__device__ float g_cbn[KDICT * DIMZ];
__device__ float g_avg[KDICT];
__device__ float g_kldd;
__device__ float g_kldc;

// ---------------------------------------------------------------- zero accums
__global__ void k_zero() {
    int t = threadIdx.x;
    if (t < KDICT) g_avg[t] = 0.0f;
    if (t == 0) { g_kldd = 0.0f; g_kldc = 0.0f; }
}

// ------------------------------------------------- L2-normalize codebook rows
__global__ void k_norm(const float* __restrict__ cb) {
    int row = blockIdx.x;      // 512 blocks
    int t = threadIdx.x;       // 256 threads
    float c = cb[row * DIMZ + t];
    float s = c * c;
    #pragma unroll
    for (int o = 16; o; o >>= 1) s += __shfl_xor_sync(0xffffffffu, s, o);
    __shared__ float ws[8];
    if ((t & 31) == 0) ws[t >> 5] = s;
    __syncthreads();
    float tot = 0.0f;
    #pragma unroll
    for (int i = 0; i < 8; i++) tot += ws[i];
    g_cbn[row * DIMZ + t] = c * (1.0f / sqrtf(tot));
}

// --------------------------------------------------------------- fused main
// One block = 32 rows (fixed b,w ; h = 0..31). 256 threads. 1024 blocks.
__global__ __launch_bounds__(256, 1)
void k_main(const float* __restrict__ z, const float* __restrict__ kappa,
            const float* __restrict__ gu, float* __restrict__ out) {
    extern __shared__ float sm[];
    float* sZ    = sm;                    // [d][32]
    float* sCB   = sm + 8192;             // [k][65] during GEMM1
    float* L     = sm + 8192;             // [32][512] logits / t2 / GEMM2 stage
    float* E     = sm + 8192 + 16384;     // [32][512] e / encodings
    float* sProb = sm + 8192 + 33280;     // [512]
    float* sZi2  = sProb + 512;           // [32]
    float* sRed  = sZi2 + 32;             // [16]

    const int t    = threadIdx.x;
    const int lane = t & 31;
    const int w8   = t >> 5;
    const int blk  = blockIdx.x;
    const int b    = blk >> 5;
    const int w    = blk & 31;
    const int R0   = blk << 5;

    const float* zb = z + (size_t)b * 262144 + w * 32;   // + d*1024 + h

    // ---- phase 0: load z tile (coalesced), zero sProb
    #pragma unroll
    for (int dd = 0; dd < 32; dd++) {
        int d = (w8 << 5) + dd;
        sZ[d * 32 + lane] = zb[d * 1024 + lane];
    }
    sProb[t] = 0.0f;
    sProb[t + 256] = 0.0f;

    const float kq = fminf(fmaxf(kappa[0], 1e-5f), 1e5f);

    // ---- GEMM1: logits[32][512] = z_tile @ cbn^T
    const int tr = t >> 6;        // 0..3  -> rows tr*8 .. tr*8+7
    const int tk = t & 63;        // 0..63 -> k = tk + 64*j
    float acc[8][8];
    #pragma unroll
    for (int i = 0; i < 8; i++)
        #pragma unroll
        for (int j = 0; j < 8; j++) acc[i][j] = 0.0f;

    for (int dt = 0; dt < 256; dt += 64) {
        __syncthreads();
        // stage cbn[:, dt:dt+64] into sCB[k][65]
        #pragma unroll
        for (int i = 0; i < 32; i++) {
            int f = t + (i << 8);           // 0..8191
            int k = f >> 4, d4 = f & 15;
            const float4 v = *(const float4*)(g_cbn + k * DIMZ + dt + (d4 << 2));
            float* dst = sCB + k * 65 + (d4 << 2);
            dst[0] = v.x; dst[1] = v.y; dst[2] = v.z; dst[3] = v.w;
        }
        __syncthreads();
        #pragma unroll 4
        for (int dd = 0; dd < 64; dd++) {
            float zf[8];
            float4 z0 = *(float4*)(sZ + (dt + dd) * 32 + (tr << 3));
            float4 z1 = *(float4*)(sZ + (dt + dd) * 32 + (tr << 3) + 4);
            zf[0] = z0.x; zf[1] = z0.y; zf[2] = z0.z; zf[3] = z0.w;
            zf[4] = z1.x; zf[5] = z1.y; zf[6] = z1.z; zf[7] = z1.w;
            float cf[8];
            #pragma unroll
            for (int j = 0; j < 8; j++) cf[j] = sCB[(tk + (j << 6)) * 65 + dd];
            #pragma unroll
            for (int i = 0; i < 8; i++)
                #pragma unroll
                for (int j = 0; j < 8; j++)
                    acc[i][j] = fmaf(zf[i], cf[j], acc[i][j]);
        }
    }
    __syncthreads();
    #pragma unroll
    for (int i = 0; i < 8; i++)
        #pragma unroll
        for (int j = 0; j < 8; j++)
            L[((tr << 3) + i) * KDICT + tk + (j << 6)] = acc[i][j] * kq;
    __syncthreads();

    // ---- softmax + gumbel: warp w8 owns rows w8*4 .. +3
    float kd_part = 0.0f;
    float probloc[16];
    #pragma unroll
    for (int q = 0; q < 16; q++) probloc[q] = 0.0f;

    for (int rr = 0; rr < 4; rr++) {
        const int r = (w8 << 2) + rr;
        float* Lr = L + r * KDICT;
        float* Er = E + r * KDICT;
        const float* gr = gu + (size_t)(R0 + r) * KDICT;

        float m = -1e30f;
        #pragma unroll
        for (int q = 0; q < 16; q++) m = fmaxf(m, Lr[lane + (q << 5)]);
        #pragma unroll
        for (int o = 16; o; o >>= 1) m = fmaxf(m, __shfl_xor_sync(0xffffffffu, m, o));

        float Zs = 0.0f, Ss = 0.0f, m2 = -1e30f;
        #pragma unroll
        for (int q = 0; q < 16; q++) {
            int k = lane + (q << 5);
            float lc = fmaxf(Lr[k] - m, -50.0f);      // upper clip never active
            float e = __expf(lc);
            Zs += e; Ss += e * lc;
            float u = gr[k];
            float g = -__logf(1e-10f - __logf(u + 1e-10f));
            float t2 = (lc + g) * 2.0f;               // /TEMPERATURE
            Er[k] = e;
            Lr[k] = t2;
            m2 = fmaxf(m2, t2);
        }
        #pragma unroll
        for (int o = 16; o; o >>= 1) {
            Zs += __shfl_xor_sync(0xffffffffu, Zs, o);
            Ss += __shfl_xor_sync(0xffffffffu, Ss, o);
            m2 = fmaxf(m2, __shfl_xor_sync(0xffffffffu, m2, o));
        }
        float zi = 1.0f / Zs;
        if (lane == 0) kd_part += Ss * zi - __logf(Zs);   // sum p*logp for row

        float Z2 = 0.0f;
        #pragma unroll
        for (int q = 0; q < 16; q++) {
            int k = lane + (q << 5);
            probloc[q] += Er[k] * zi;                 // probabilities accum
            float eg = __expf(Lr[k] - m2);
            Z2 += eg;
            Er[k] = eg;                               // unnormalized encodings
        }
        #pragma unroll
        for (int o = 16; o; o >>= 1) Z2 += __shfl_xor_sync(0xffffffffu, Z2, o);
        if (lane == 0) sZi2[r] = 1.0f / Z2;
    }
    #pragma unroll
    for (int q = 0; q < 16; q++) atomicAdd(sProb + lane + (q << 5), probloc[q]);
    __syncthreads();
    atomicAdd(g_avg + t, sProb[t]);
    atomicAdd(g_avg + t + 256, sProb[t + 256]);

    // ---- GEMM2: zq[32][256] = enc @ cbn    (enc = E * (1/Z2), folded at end)
    float acc2[8][4];
    #pragma unroll
    for (int i = 0; i < 8; i++)
        #pragma unroll
        for (int jj = 0; jj < 4; jj++) acc2[i][jj] = 0.0f;

    for (int kt = 0; kt < 512; kt += 64) {
        __syncthreads();
        // stage cbn[kt:kt+64][0:256] into L region [kk][256]
        #pragma unroll
        for (int i = 0; i < 16; i++) {
            int f = t + (i << 8);            // 0..4095
            int kk = f >> 6, c4 = f & 63;
            *(float4*)(L + kk * 256 + (c4 << 2)) =
                *(const float4*)(g_cbn + (size_t)(kt + kk) * DIMZ + (c4 << 2));
        }
        __syncthreads();
        #pragma unroll 4
        for (int kk = 0; kk < 64; kk++) {
            float ef[8];
            #pragma unroll
            for (int i = 0; i < 8; i++)
                ef[i] = E[((tr << 3) + i) * KDICT + kt + kk];   // broadcast
            float cf2[4];
            #pragma unroll
            for (int jj = 0; jj < 4; jj++) cf2[jj] = L[kk * 256 + tk + (jj << 6)];
            #pragma unroll
            for (int i = 0; i < 8; i++)
                #pragma unroll
                for (int jj = 0; jj < 4; jj++)
                    acc2[i][jj] = fmaf(ef[i], cf2[jj], acc2[i][jj]);
        }
    }

    // ---- epilogue: scale by 1/Z2, write z_to_decoder, kld_continuous partial
    float kldc_part = 0.0f;
    float zinv[8];
    #pragma unroll
    for (int i = 0; i < 8; i++) zinv[i] = sZi2[(tr << 3) + i];

    #pragma unroll
    for (int jj = 0; jj < 4; jj++) {
        int d = tk + (jj << 6);
        const float* zp = zb + d * 1024 + (tr << 3);
        float4 zv0 = *(const float4*)zp;
        float4 zv1 = *(const float4*)(zp + 4);
        float zr[8] = {zv0.x, zv0.y, zv0.z, zv0.w, zv1.x, zv1.y, zv1.z, zv1.w};
        float v[8];
        #pragma unroll
        for (int i = 0; i < 8; i++) {
            float zq = acc2[i][jj] * zinv[i];
            v[i] = zq;
            kldc_part += zr[i] * (zr[i] - zq);
        }
        float* op = out + (size_t)b * 262144 + ((size_t)d << 10) + w * 32 + (tr << 3);
        *(float4*)op       = make_float4(v[0], v[1], v[2], v[3]);
        *(float4*)(op + 4) = make_float4(v[4], v[5], v[6], v[7]);
    }

    // ---- block reduce kldc / kldd, single atomic each
    float vc = kldc_part, vk = kd_part;
    #pragma unroll
    for (int o = 16; o; o >>= 1) {
        vc += __shfl_xor_sync(0xffffffffu, vc, o);
        vk += __shfl_xor_sync(0xffffffffu, vk, o);
    }
    if (lane == 0) { sRed[w8] = vc; sRed[8 + w8] = vk; }
    __syncthreads();
    if (t == 0) {
        float sc = 0.0f, sk = 0.0f;
        #pragma unroll
        for (int i = 0; i < 8; i++) { sc += sRed[i]; sk += sRed[8 + i]; }
        atomicAdd(&g_kldc, sc);
        atomicAdd(&g_kldd, sk);
    }
}

// ----------------------------------------------------------------- finalize
__global__ void k_fin(const float* __restrict__ kappa, float* __restrict__ out,
                      int out_size) {
    int t = threadIdx.x;  // 512
    float a = g_avg[t] * (1.0f / (float)NROWS);
    a = fmaxf(a, 1e-10f);
    float term = a * logf(a + 1e-10f);
    #pragma unroll
    for (int o = 16; o; o >>= 1) term += __shfl_xor_sync(0xffffffffu, term, o);
    __shared__ float ws[16];
    if ((t & 31) == 0) ws[t >> 5] = term;
    __syncthreads();
    if (t == 0) {
        float s = 0.0f;
        #pragma unroll
        for (int i = 0; i < 16; i++) s += ws[i];
        float kq = fminf(fmaxf(kappa[0], 1e-5f), 1e5f);
        float loss = (g_kldd + g_kldc * kq) * (1.0f / (float)BSZ);
        if (out_size >= 8388609) out[8388608] = loss;
        if (out_size >= 8388610) out[8388609] = expf(-s);
    }
}

// ------------------------------------------------------------------ launcher
extern "C" void kernel_launch(void* const* d_in, const int* in_sizes, int n_in,
                              void* d_out, int out_size) {
    const float* z     = (const float*)d_in[0];
    const float* kappa = (const float*)d_in[1];
    const float* cb    = (const float*)d_in[2];
    const float* gu    = (const float*)d_in[3];
    float* out = (float*)d_out;

    cudaFuncSetAttribute(k_main, cudaFuncAttributeMaxDynamicSharedMemorySize,
                         SM_BYTES);
    k_zero<<<1, 512>>>();
    k_norm<<<512, 256>>>(cb);
    k_main<<<1024, 256, SM_BYTES>>>(z, kappa, gu, out);
    k_fin<<<1, 512>>>(kappa, out, out_size);
}

// round 9
// speedup vs baseline: 1.5743x; 1.5738x over previous
#include <cuda_runtime.h>
#include <cuda_bf16.h>
#include <cstdint>
#include <math.h>

#define KD 512
#define DZ 256
#define NR 32768

// smem map (bytes): RA [0,69632)  RB [69632,200704)  MISC [200704,203552)
#define RBOFF 69632
#define MISCOFF 200704
#define SMTOT 203552

__device__ __forceinline__ uint32_t s2u(const void* p){
    uint32_t a;
    asm("{ .reg .u64 t; cvta.to.shared.u64 t,%1; cvt.u32.u64 %0,t; }" : "=r"(a) : "l"(p));
    return a;
}
__device__ __forceinline__ void ldsm4(uint32_t r[4], uint32_t a){
    asm volatile("ldmatrix.sync.aligned.m8n8.x4.shared.b16 {%0,%1,%2,%3}, [%4];"
        : "=r"(r[0]),"=r"(r[1]),"=r"(r[2]),"=r"(r[3]) : "r"(a));
}
__device__ __forceinline__ void mma_bf(float d[4], const uint32_t a[4], uint32_t b0, uint32_t b1){
    asm volatile("mma.sync.aligned.m16n8k16.row.col.f32.bf16.bf16.f32 "
        "{%0,%1,%2,%3},{%4,%5,%6,%7},{%8,%9},{%0,%1,%2,%3};"
        : "+f"(d[0]),"+f"(d[1]),"+f"(d[2]),"+f"(d[3])
        : "r"(a[0]),"r"(a[1]),"r"(a[2]),"r"(a[3]),"r"(b0),"r"(b1));
}
__device__ __forceinline__ uint32_t packpair(float lo, float hi){
    uint32_t r; asm("cvt.rn.bf16x2.f32 %0, %1, %2;" : "=r"(r) : "f"(hi), "f"(lo)); return r;
}
__device__ __forceinline__ float lof(float x){
    return x - __bfloat162float(__float2bfloat16(x));
}

__device__ uint32_t g_zh[NR*128];     // z hi pairs  [row][kpair]
__device__ uint32_t g_zl[NR*128];
__device__ uint32_t g_c1h[KD*128];    // kq*cbn [n=512][kpair=128]
__device__ uint32_t g_c1l[KD*128];
__device__ uint32_t g_c2h[DZ*256];    // cbn^T  [d=256][jpair=256]
__device__ uint32_t g_c2l[DZ*256];
__device__ float    g_cbn[KD*DZ];
__device__ float    g_avg[KD];
__device__ float    g_kldd, g_kldc;

__global__ void k_zero(){
    int t=threadIdx.x;
    if (t<KD) g_avg[t]=0.f;
    if (t==0){ g_kldd=0.f; g_kldc=0.f; }
}

__global__ void k_norm(const float* __restrict__ cb, const float* __restrict__ kappa){
    __shared__ float rowb[256];
    __shared__ float ws[8];
    int j=blockIdx.x, t=threadIdx.x;
    float c=cb[j*DZ+t], s=c*c;
    #pragma unroll
    for(int o=16;o;o>>=1) s += __shfl_xor_sync(0xffffffffu,s,o);
    if((t&31)==0) ws[t>>5]=s;
    __syncthreads();
    float tot=0.f;
    #pragma unroll
    for(int i=0;i<8;i++) tot+=ws[i];
    float cn=c*(1.f/sqrtf(tot));
    g_cbn[j*DZ+t]=cn;
    float kq=fminf(fmaxf(kappa[0],1e-5f),1e5f);
    rowb[t]=cn*kq;
    __syncthreads();
    if(t<128){
        float a=rowb[2*t], b=rowb[2*t+1];
        g_c1h[j*128+t]=packpair(a,b);
        g_c1l[j*128+t]=packpair(lof(a),lof(b));
    }
}

__global__ void k_c2(){
    int d=blockIdx.x, t=threadIdx.x;   // t = jpair
    float a=g_cbn[(2*t)*DZ+d], b=g_cbn[(2*t+1)*DZ+d];
    g_c2h[d*256+t]=packpair(a,b);
    g_c2l[d*256+t]=packpair(lof(a),lof(b));
}

__global__ void k_zprep(const float* __restrict__ z){
    __shared__ float sZ[DZ*33];
    int t=threadIdx.x, blk=blockIdx.x;
    int b=blk>>5, w=blk&31;
    const float* zb = z + (size_t)b*262144 + w*32;
    #pragma unroll
    for(int i=0;i<32;i++){ int f=t+(i<<8); int d=f>>5,h=f&31; sZ[d*33+h]=zb[d*1024+h]; }
    __syncthreads();
    #pragma unroll
    for(int i=0;i<16;i++){
        int q=t+(i<<8); int r=q>>7, j=q&127;
        float x=sZ[(2*j)*33+r], y=sZ[(2*j+1)*33+r];
        size_t idx=(size_t)(blk*32+r)*128+j;
        g_zh[idx]=packpair(x,y);
        g_zl[idx]=packpair(lof(x),lof(y));
    }
}

__global__ __launch_bounds__(256,1)
void k_main(const float* __restrict__ gu, const float* __restrict__ z,
            float* __restrict__ out){
    extern __shared__ char sm[];
    const uint32_t smb=s2u(sm);
    float* MISC=(float*)(sm+MISCOFF);
    float* sZs=MISC; float* sSs=MISC+64; float* sZ2=MISC+128;
    float* sRed=MISC+704;
    const int t=threadIdx.x, lane=t&31, w=t>>5;
    const int mg=w&1, ns=w>>1;
    const int g=lane>>2, tq=lane&3;
    const int R0=blockIdx.x<<6;
    if(t<64){ sZs[t]=0.f; sSs[t]=0.f; sZ2[t]=0.f; }

    // stage A (z rows, hi+lo), 32 16B-granules per row, swizzled
    #pragma unroll
    for(int i=0;i<16;i++){
        int q=t+(i<<8); int arr=q>>11, rem=q&2047, m=rem>>5, gr=rem&31;
        const uint4* src = arr ? (const uint4*)g_zl : (const uint4*)g_zh;
        uint4 v = src[(size_t)(R0+m)*32+gr];
        int swz=(gr&24)|((gr^m)&7);
        *(uint4*)(sm + arr*32768 + m*512 + (swz<<4)) = v;
    }
    const int sub=lane>>3, rro=(lane&7)+((sub&1)<<3), gpl=sub>>1;

    float a1[2][16][4];
    #pragma unroll
    for(int a=0;a<2;a++)
        #pragma unroll
        for(int b=0;b<16;b++)
            #pragma unroll
            for(int c=0;c<4;c++) a1[a][b][c]=0.f;

    // -------- GEMM1: logits[64][512] --------
    for(int kc=0;kc<4;kc++){
        __syncthreads();
        #pragma unroll
        for(int i=0;i<32;i++){
            int q=t+(i<<8); int arr=q>>12, rem=q&4095, n=rem>>3, gr=rem&7;
            const uint4* src = arr ? (const uint4*)g_c1l : (const uint4*)g_c1h;
            uint4 v = src[n*32 + kc*8 + gr];
            *(uint4*)(sm + RBOFF + arr*65536 + n*128 + ((gr^(n&7))<<4)) = v;
        }
        __syncthreads();
        #pragma unroll
        for(int ks=0;ks<4;ks++){
            int ggA=kc*8+2*ks+gpl, ggB=2*ks+gpl;
            uint32_t ah[2][4], al[2][4];
            #pragma unroll
            for(int mt=0;mt<2;mt++){
                int rr=mg*32+mt*16+rro;
                uint32_t ad=smb + rr*512 + ((((ggA&24)|((ggA^rr)&7)))<<4);
                ldsm4(ah[mt],ad); ldsm4(al[mt],ad+32768);
            }
            #pragma unroll
            for(int nt2=0;nt2<8;nt2++){
                int rrB=ns*128+nt2*16+rro;
                uint32_t bd=smb + RBOFF + rrB*128 + ((ggB^(rrB&7))<<4);
                uint32_t bh[4], bl[4];
                ldsm4(bh,bd); ldsm4(bl,bd+65536);
                #pragma unroll
                for(int mt=0;mt<2;mt++){
                    mma_bf(a1[mt][2*nt2],   ah[mt], bh[0], bh[2]);
                    mma_bf(a1[mt][2*nt2+1], ah[mt], bh[1], bh[3]);
                    mma_bf(a1[mt][2*nt2],   al[mt], bh[0], bh[2]);
                    mma_bf(a1[mt][2*nt2+1], al[mt], bh[1], bh[3]);
                    mma_bf(a1[mt][2*nt2],   ah[mt], bl[0], bl[2]);
                    mma_bf(a1[mt][2*nt2+1], ah[mt], bl[1], bl[3]);
                }
            }
        }
    }
    __syncthreads();

    // -------- softmax + gumbel (from regs); e->RA bf16, eg->RB bf16 hi/lo --------
    #pragma unroll
    for(int mt=0;mt<2;mt++){
        int r0=mg*32+mt*16+g, r1=r0+8;
        float Zs0=0,Ss0=0,Q0=0, Zs1=0,Ss1=0,Q1=0;
        #pragma unroll
        for(int nt=0;nt<16;nt++){
            int col=ns*128+nt*8+2*tq;
            float2 u0=*(const float2*)(gu+(size_t)(R0+r0)*512+col);
            float2 u1=*(const float2*)(gu+(size_t)(R0+r1)*512+col);
            float* dd=a1[mt][nt];
            float e0=__expf(dd[0]), e1=__expf(dd[1]);
            float e2=__expf(dd[2]), e3=__expf(dd[3]);
            Zs0+=e0+e1; Ss0+=e0*dd[0]+e1*dd[1];
            Zs1+=e2+e3; Ss1+=e2*dd[2]+e3*dd[3];
            *(uint32_t*)(sm + r0*1040 + col*2)=packpair(e0,e1);
            *(uint32_t*)(sm + r1*1040 + col*2)=packpair(e2,e3);
            float w0=-__logf(u0.x+1e-10f), w1=-__logf(u0.y+1e-10f);
            float w2=-__logf(u1.x+1e-10f), w3=-__logf(u1.y+1e-10f);
            float v0=e0*__frcp_rn(w0+1e-10f), v1=e1*__frcp_rn(w1+1e-10f);
            float v2=e2*__frcp_rn(w2+1e-10f), v3=e3*__frcp_rn(w3+1e-10f);
            float q0=v0*v0,q1=v1*v1,q2=v2*v2,q3=v3*v3;
            Q0+=q0+q1; Q1+=q2+q3;
            int gf=col>>3; int swz=(gf&56)|((gf^(r0&7))&7);
            uint32_t off=(uint32_t)(swz<<4)+4*tq;
            *(uint32_t*)(sm + RBOFF + r0*1024 + off)=packpair(q0,q1);
            *(uint32_t*)(sm + RBOFF + 65536 + r0*1024 + off)=packpair(lof(q0),lof(q1));
            *(uint32_t*)(sm + RBOFF + r1*1024 + off)=packpair(q2,q3);
            *(uint32_t*)(sm + RBOFF + 65536 + r1*1024 + off)=packpair(lof(q2),lof(q3));
        }
        atomicAdd(&sZs[r0],Zs0); atomicAdd(&sSs[r0],Ss0); atomicAdd(&sZ2[r0],Q0);
        atomicAdd(&sZs[r1],Zs1); atomicAdd(&sSs[r1],Ss1); atomicAdd(&sZ2[r1],Q1);
    }
    __syncthreads();
    if(t<64){
        float zs=sZs[t], inv=1.f/zs;
        float kd=sSs[t]*inv-__logf(zs);
        sZs[t]=inv;
        sZ2[t]=1.f/sZ2[t];
        #pragma unroll
        for(int o=16;o;o>>=1) kd+=__shfl_xor_sync(0xffffffffu,kd,o);
        if(lane==0) atomicAdd(&g_kldd,kd);
    }
    __syncthreads();
    {   // avg_probs columns (e bf16 * 1/Zs)
        float p0=0.f,p1=0.f;
        #pragma unroll 8
        for(int r=0;r<64;r++){
            float zi=sZs[r];
            p0=fmaf(__bfloat162float(*(const __nv_bfloat16*)(sm+r*1040+t*2)),zi,p0);
            p1=fmaf(__bfloat162float(*(const __nv_bfloat16*)(sm+r*1040+(t+256)*2)),zi,p1);
        }
        atomicAdd(&g_avg[t],p0); atomicAdd(&g_avg[t+256],p1);
    }

    // -------- GEMM2: zq[64][256] = eg @ cbn --------
    float a2[2][8][4];
    #pragma unroll
    for(int a=0;a<2;a++)
        #pragma unroll
        for(int b=0;b<8;b++)
            #pragma unroll
            for(int c=0;c<4;c++) a2[a][b][c]=0.f;

    for(int kc=0;kc<8;kc++){
        __syncthreads();
        #pragma unroll
        for(int i=0;i<16;i++){
            int q=t+(i<<8); int arr=q>>11, rem=q&2047, dd=rem>>3, gr=rem&7;
            const uint4* src = arr ? (const uint4*)g_c2l : (const uint4*)g_c2h;
            uint4 v = src[dd*64 + kc*8 + gr];
            *(uint4*)(sm + arr*32768 + dd*128 + ((gr^(dd&7))<<4)) = v;
        }
        __syncthreads();
        #pragma unroll
        for(int ks=0;ks<4;ks++){
            int ggE=kc*8+2*ks+gpl, ggB=2*ks+gpl;
            uint32_t eh[2][4], el[2][4];
            #pragma unroll
            for(int mt=0;mt<2;mt++){
                int rr=mg*32+mt*16+rro;
                uint32_t ad=smb + RBOFF + rr*1024 + ((((ggE&56)|((ggE^rr)&7)))<<4);
                ldsm4(eh[mt],ad); ldsm4(el[mt],ad+65536);
            }
            #pragma unroll
            for(int nt2=0;nt2<4;nt2++){
                int rrB=ns*64+nt2*16+rro;
                uint32_t bd=smb + rrB*128 + ((ggB^(rrB&7))<<4);
                uint32_t bh[4], bl[4];
                ldsm4(bh,bd); ldsm4(bl,bd+32768);
                #pragma unroll
                for(int mt=0;mt<2;mt++){
                    mma_bf(a2[mt][2*nt2],   eh[mt], bh[0], bh[2]);
                    mma_bf(a2[mt][2*nt2+1], eh[mt], bh[1], bh[3]);
                    mma_bf(a2[mt][2*nt2],   el[mt], bh[0], bh[2]);
                    mma_bf(a2[mt][2*nt2+1], el[mt], bh[1], bh[3]);
                    mma_bf(a2[mt][2*nt2],   eh[mt], bl[0], bl[2]);
                    mma_bf(a2[mt][2*nt2+1], eh[mt], bl[1], bl[3]);
                }
            }
        }
    }
    __syncthreads();

    // -------- epilogue: scale, transpose, coalesced store + kldc --------
    float* sT=(float*)sm;   // [256 d][66]
    #pragma unroll
    for(int mt=0;mt<2;mt++){
        int r0=mg*32+mt*16+g, r1=r0+8;
        float zi0=sZ2[r0], zi1=sZ2[r1];
        #pragma unroll
        for(int nt=0;nt<8;nt++){
            int d0=ns*64+nt*8+2*tq;
            float* dd=a2[mt][nt];
            sT[d0*66+r0]=dd[0]*zi0; sT[(d0+1)*66+r0]=dd[1]*zi0;
            sT[d0*66+r1]=dd[2]*zi1; sT[(d0+1)*66+r1]=dd[3]*zi1;
        }
    }
    __syncthreads();
    size_t base=((size_t)(R0>>10))*262144 + (size_t)(R0&1023);
    float kcc=0.f;
    #pragma unroll
    for(int i=0;i<64;i++){
        int q=t+(i<<8); int d=q>>6, r=q&63;
        float v=sT[d*66+r];
        size_t gi=base+(size_t)d*1024+r;
        float zv=z[gi];
        out[gi]=v;
        kcc=fmaf(zv,zv-v,kcc);
    }
    #pragma unroll
    for(int o=16;o;o>>=1) kcc+=__shfl_xor_sync(0xffffffffu,kcc,o);
    if(lane==0) sRed[w]=kcc;
    __syncthreads();
    if(t==0){
        float s=0.f;
        #pragma unroll
        for(int i=0;i<8;i++) s+=sRed[i];
        atomicAdd(&g_kldc,s);
    }
}

__global__ void k_fin(const float* __restrict__ kappa, float* __restrict__ out, int out_size){
    int t=threadIdx.x;
    float a=g_avg[t]*(1.f/(float)NR);
    a=fmaxf(a,1e-10f);
    float term=a*logf(a+1e-10f);
    #pragma unroll
    for(int o=16;o;o>>=1) term+=__shfl_xor_sync(0xffffffffu,term,o);
    __shared__ float ws[16];
    if((t&31)==0) ws[t>>5]=term;
    __syncthreads();
    if(t==0){
        float s=0.f;
        #pragma unroll
        for(int i=0;i<16;i++) s+=ws[i];
        float kq=fminf(fmaxf(kappa[0],1e-5f),1e5f);
        float loss=(g_kldd+g_kldc*kq)*(1.f/32.f);
        if(out_size>=8388609) out[8388608]=loss;
        if(out_size>=8388610) out[8388609]=expf(-s);
    }
}

extern "C" void kernel_launch(void* const* d_in, const int* in_sizes, int n_in,
                              void* d_out, int out_size){
    const float* z=(const float*)d_in[0];
    const float* kappa=(const float*)d_in[1];
    const float* cb=(const float*)d_in[2];
    const float* gu=(const float*)d_in[3];
    float* out=(float*)d_out;
    cudaFuncSetAttribute(k_main, cudaFuncAttributeMaxDynamicSharedMemorySize, SMTOT);
    k_zero<<<1,512>>>();
    k_norm<<<512,256>>>(cb,kappa);
    k_c2<<<256,256>>>();
    k_zprep<<<1024,256>>>(z);
    k_main<<<512,256,SMTOT>>>(gu,z,out);
    k_fin<<<1,512>>>(kappa,out,out_size);
}

// round 10
// speedup vs baseline: 2.1425x; 1.3609x over previous
#include <cuda_runtime.h>
#include <cuda_bf16.h>
#include <cstdint>
#include <math.h>

#define KD 512
#define DZ 256
#define NR 32768

// smem map (bytes): RA [0,69632)  RB [69632,200704)  MISC [200704,203552)
#define RBOFF 69632
#define MISCOFF 200704
#define SMTOT 203552

__device__ __forceinline__ uint32_t s2u(const void* p){
    uint32_t a;
    asm("{ .reg .u64 t; cvta.to.shared.u64 t,%1; cvt.u32.u64 %0,t; }" : "=r"(a) : "l"(p));
    return a;
}
__device__ __forceinline__ void ldsm4(uint32_t r[4], uint32_t a){
    asm volatile("ldmatrix.sync.aligned.m8n8.x4.shared.b16 {%0,%1,%2,%3}, [%4];"
        : "=r"(r[0]),"=r"(r[1]),"=r"(r[2]),"=r"(r[3]) : "r"(a));
}
__device__ __forceinline__ void mma_bf(float d[4], const uint32_t a[4], uint32_t b0, uint32_t b1){
    asm volatile("mma.sync.aligned.m16n8k16.row.col.f32.bf16.bf16.f32 "
        "{%0,%1,%2,%3},{%4,%5,%6,%7},{%8,%9},{%0,%1,%2,%3};"
        : "+f"(d[0]),"+f"(d[1]),"+f"(d[2]),"+f"(d[3])
        : "r"(a[0]),"r"(a[1]),"r"(a[2]),"r"(a[3]),"r"(b0),"r"(b1));
}
__device__ __forceinline__ void cpa16(uint32_t dst, const void* src){
    asm volatile("cp.async.cg.shared.global [%0], [%1], 16;" :: "r"(dst), "l"(src));
}
#define CPA_COMMIT() asm volatile("cp.async.commit_group;" ::: "memory")
#define CPA_WAIT0()  asm volatile("cp.async.wait_group 0;" ::: "memory")
#define CPA_WAIT1()  asm volatile("cp.async.wait_group 1;" ::: "memory")

__device__ __forceinline__ uint32_t packpair(float lo, float hi){
    uint32_t r; asm("cvt.rn.bf16x2.f32 %0, %1, %2;" : "=r"(r) : "f"(hi), "f"(lo)); return r;
}
__device__ __forceinline__ float lof(float x){
    return x - __bfloat162float(__float2bfloat16(x));
}

__device__ uint32_t g_c1h[KD*128];    // kq*cbn [n=512][kpair=128]
__device__ uint32_t g_c1l[KD*128];
__device__ uint32_t g_c2h[DZ*256];    // cbn^T  [d=256][jpair=256]
__device__ uint32_t g_c2l[DZ*256];
__device__ float    g_cbn[KD*DZ];
__device__ float    g_avg[KD];
__device__ float    g_kldd, g_kldc;

__global__ void k_zero(){
    int t=threadIdx.x;
    if (t<KD) g_avg[t]=0.f;
    if (t==0){ g_kldd=0.f; g_kldc=0.f; }
}

__global__ void k_norm(const float* __restrict__ cb, const float* __restrict__ kappa){
    __shared__ float rowb[256];
    __shared__ float ws[8];
    int j=blockIdx.x, t=threadIdx.x;
    float c=cb[j*DZ+t], s=c*c;
    #pragma unroll
    for(int o=16;o;o>>=1) s += __shfl_xor_sync(0xffffffffu,s,o);
    if((t&31)==0) ws[t>>5]=s;
    __syncthreads();
    float tot=0.f;
    #pragma unroll
    for(int i=0;i<8;i++) tot+=ws[i];
    float cn=c*(1.f/sqrtf(tot));
    g_cbn[j*DZ+t]=cn;
    float kq=fminf(fmaxf(kappa[0],1e-5f),1e5f);
    rowb[t]=cn*kq;
    __syncthreads();
    if(t<128){
        float a=rowb[2*t], b=rowb[2*t+1];
        g_c1h[j*128+t]=packpair(a,b);
        g_c1l[j*128+t]=packpair(lof(a),lof(b));
    }
}

__global__ void k_c2(){
    int d=blockIdx.x, t=threadIdx.x;   // t = jpair
    float a=g_cbn[(2*t)*DZ+d], b=g_cbn[(2*t+1)*DZ+d];
    g_c2h[d*256+t]=packpair(a,b);
    g_c2l[d*256+t]=packpair(lof(a),lof(b));
}

// ---- staging helpers (cp.async, one buffer each) ----
__device__ __forceinline__ void stage_b1(uint32_t smb, int t, int kc, const uint32_t* src, uint32_t dstoff){
    #pragma unroll
    for(int i=0;i<16;i++){
        int q=t+(i<<8); int n=q>>3, gr=q&7;
        cpa16(smb + dstoff + n*128 + ((gr^(n&7))<<4),
              (const char*)src + (size_t)(n*32 + kc*8 + gr)*16);
    }
}
__device__ __forceinline__ void stage_b2(uint32_t smb, int t, int kc, const uint32_t* src, uint32_t dstoff){
    #pragma unroll
    for(int i=0;i<8;i++){
        int q=t+(i<<8); int dd=q>>3, gr=q&7;
        cpa16(smb + dstoff + dd*128 + ((gr^(dd&7))<<4),
              (const char*)src + (size_t)(dd*64 + kc*8 + gr)*16);
    }
}

__global__ __launch_bounds__(256,1)
void k_main(const float* __restrict__ gu, const float* __restrict__ z,
            float* __restrict__ out){
    extern __shared__ char sm[];
    const uint32_t smb=s2u(sm);
    float* MISC=(float*)(sm+MISCOFF);
    float* sZs=MISC; float* sSs=MISC+64; float* sZ2=MISC+128;
    float* sRed=MISC+704;
    const int t=threadIdx.x, lane=t&31, w=t>>5;
    const int mg=w&1, ns=w>>1;
    const int g=lane>>2, tq=lane&3;
    const int R0=blockIdx.x<<6;
    if(t<64){ sZs[t]=0.f; sSs[t]=0.f; sZ2[t]=0.f; }

    const size_t bb=(size_t)(R0>>10);
    const int wh0=R0&1023;
    const float* zb = z + bb*262144 + wh0;

    // ---- G0: z slab -> sZ (RB upper, 64KB); G1: bh(0) -> RB lower ----
    #pragma unroll
    for(int i=0;i<16;i++){
        int q=t+(i<<8); int d=q>>4, j4=q&15;
        cpa16(smb + RBOFF + 65536 + (q<<4),
              (const char*)zb + ((size_t)d*4096 + j4*16));
    }
    CPA_COMMIT();
    stage_b1(smb,t,0,g_c1h,RBOFF);       CPA_COMMIT();   // bh(0)
    CPA_WAIT1();  __syncthreads();                        // z ready

    // ---- pack A tiles (hi at RA[0,32K), lo at RA[32K,64K)) ----
    {
        const float* sZf=(const float*)(sm + RBOFF + 65536);
        #pragma unroll
        for(int i=0;i<8;i++){
            int m=(t&31)+((i&1)<<5);
            int gr=(t>>5)+((i>>1)<<3);
            float v[8];
            #pragma unroll
            for(int c=0;c<8;c++) v[c]=sZf[(8*gr+c)*64 + m];
            int swz=(gr&24)|((gr^m)&7);
            uint32_t off=(uint32_t)(m*512 + (swz<<4));
            *(uint4*)(sm + off)=make_uint4(packpair(v[0],v[1]),packpair(v[2],v[3]),
                                           packpair(v[4],v[5]),packpair(v[6],v[7]));
            *(uint4*)(sm + 32768 + off)=make_uint4(packpair(lof(v[0]),lof(v[1])),packpair(lof(v[2]),lof(v[3])),
                                                   packpair(lof(v[4]),lof(v[5])),packpair(lof(v[6]),lof(v[7])));
        }
    }
    __syncthreads();                                      // sZ dead
    stage_b1(smb,t,0,g_c1l,RBOFF+65536); CPA_COMMIT();    // bl(0) overwrites sZ
    CPA_WAIT1(); __syncthreads();                         // bh(0) ready

    const int sub=lane>>3, rro=(lane&7)+((sub&1)<<3), gpl=sub>>1;

    float a1[2][16][4];
    #pragma unroll
    for(int a=0;a<2;a++)
        #pragma unroll
        for(int b=0;b<16;b++)
            #pragma unroll
            for(int c=0;c<4;c++) a1[a][b][c]=0.f;

    // -------- GEMM1: logits[64][512], hi/lo pipelined --------
    for(int kc=0;kc<4;kc++){
        // p1+p2: (ah+al) x bh   (bl(kc) in flight)
        #pragma unroll
        for(int ks=0;ks<4;ks++){
            int ggA=kc*8+2*ks+gpl, ggB=2*ks+gpl;
            uint32_t ah[2][4], al[2][4];
            #pragma unroll
            for(int mt=0;mt<2;mt++){
                int rr=mg*32+mt*16+rro;
                uint32_t ad=smb + rr*512 + ((((ggA&24)|((ggA^rr)&7)))<<4);
                ldsm4(ah[mt],ad); ldsm4(al[mt],ad+32768);
            }
            #pragma unroll
            for(int nt2=0;nt2<8;nt2++){
                int rrB=ns*128+nt2*16+rro;
                uint32_t bd=smb + RBOFF + rrB*128 + ((ggB^(rrB&7))<<4);
                uint32_t bh[4];
                ldsm4(bh,bd);
                #pragma unroll
                for(int mt=0;mt<2;mt++){
                    mma_bf(a1[mt][2*nt2],   ah[mt], bh[0], bh[2]);
                    mma_bf(a1[mt][2*nt2+1], ah[mt], bh[1], bh[3]);
                    mma_bf(a1[mt][2*nt2],   al[mt], bh[0], bh[2]);
                    mma_bf(a1[mt][2*nt2+1], al[mt], bh[1], bh[3]);
                }
            }
        }
        __syncthreads();
        if(kc<3){ stage_b1(smb,t,kc+1,g_c1h,RBOFF); CPA_COMMIT(); CPA_WAIT1(); }
        else    { CPA_WAIT0(); }
        __syncthreads();                                  // bl(kc) ready
        // p3: ah x bl   (bh(kc+1) in flight)
        #pragma unroll
        for(int ks=0;ks<4;ks++){
            int ggA=kc*8+2*ks+gpl, ggB=2*ks+gpl;
            uint32_t ah[2][4];
            #pragma unroll
            for(int mt=0;mt<2;mt++){
                int rr=mg*32+mt*16+rro;
                uint32_t ad=smb + rr*512 + ((((ggA&24)|((ggA^rr)&7)))<<4);
                ldsm4(ah[mt],ad);
            }
            #pragma unroll
            for(int nt2=0;nt2<8;nt2++){
                int rrB=ns*128+nt2*16+rro;
                uint32_t bd=smb + RBOFF + 65536 + rrB*128 + ((ggB^(rrB&7))<<4);
                uint32_t bl[4];
                ldsm4(bl,bd);
                #pragma unroll
                for(int mt=0;mt<2;mt++){
                    mma_bf(a1[mt][2*nt2],   ah[mt], bl[0], bl[2]);
                    mma_bf(a1[mt][2*nt2+1], ah[mt], bl[1], bl[3]);
                }
            }
        }
        __syncthreads();
        if(kc<3){ stage_b1(smb,t,kc+1,g_c1l,RBOFF+65536); CPA_COMMIT(); CPA_WAIT1(); __syncthreads(); }
    }

    // -------- softmax + gumbel (from regs); e->RA bf16, eg->RB bf16 hi/lo --------
    #pragma unroll
    for(int mt=0;mt<2;mt++){
        int r0=mg*32+mt*16+g, r1=r0+8;
        const float* gur0 = gu + (size_t)(R0+r0)*512 + ns*128 + 2*tq;
        const float* gur1 = gu + (size_t)(R0+r1)*512 + ns*128 + 2*tq;
        float2 nu0=*(const float2*)gur0, nu1=*(const float2*)gur1;
        float Zs0=0,Ss0=0,Q0=0, Zs1=0,Ss1=0,Q1=0;
        #pragma unroll
        for(int nt=0;nt<16;nt++){
            float2 u0=nu0, u1=nu1;
            if(nt<15){ nu0=*(const float2*)(gur0+(nt+1)*8); nu1=*(const float2*)(gur1+(nt+1)*8); }
            int col=ns*128+nt*8+2*tq;
            float* dd=a1[mt][nt];
            float e0=__expf(dd[0]), e1=__expf(dd[1]);
            float e2=__expf(dd[2]), e3=__expf(dd[3]);
            Zs0+=e0+e1; Ss0+=e0*dd[0]+e1*dd[1];
            Zs1+=e2+e3; Ss1+=e2*dd[2]+e3*dd[3];
            *(uint32_t*)(sm + r0*1040 + col*2)=packpair(e0,e1);
            *(uint32_t*)(sm + r1*1040 + col*2)=packpair(e2,e3);
            float w0=-__logf(u0.x+1e-10f), w1=-__logf(u0.y+1e-10f);
            float w2=-__logf(u1.x+1e-10f), w3=-__logf(u1.y+1e-10f);
            float v0=__fdividef(e0,w0+1e-10f), v1=__fdividef(e1,w1+1e-10f);
            float v2=__fdividef(e2,w2+1e-10f), v3=__fdividef(e3,w3+1e-10f);
            float q0=v0*v0,q1=v1*v1,q2=v2*v2,q3=v3*v3;
            Q0+=q0+q1; Q1+=q2+q3;
            int gf=col>>3; int swz=(gf&56)|((gf^(r0&7))&7);
            uint32_t off=(uint32_t)(swz<<4)+4*tq;
            *(uint32_t*)(sm + RBOFF + r0*1024 + off)=packpair(q0,q1);
            *(uint32_t*)(sm + RBOFF + 65536 + r0*1024 + off)=packpair(lof(q0),lof(q1));
            *(uint32_t*)(sm + RBOFF + r1*1024 + off)=packpair(q2,q3);
            *(uint32_t*)(sm + RBOFF + 65536 + r1*1024 + off)=packpair(lof(q2),lof(q3));
        }
        atomicAdd(&sZs[r0],Zs0); atomicAdd(&sSs[r0],Ss0); atomicAdd(&sZ2[r0],Q0);
        atomicAdd(&sZs[r1],Zs1); atomicAdd(&sSs[r1],Ss1); atomicAdd(&sZ2[r1],Q1);
    }
    __syncthreads();
    if(t<64){
        float zs=sZs[t], inv=1.f/zs;
        float kd=sSs[t]*inv-__logf(zs);
        sZs[t]=inv;
        sZ2[t]=1.f/sZ2[t];
        #pragma unroll
        for(int o=16;o;o>>=1) kd+=__shfl_xor_sync(0xffffffffu,kd,o);
        if(lane==0) atomicAdd(&g_kldd,kd);
    }
    __syncthreads();
    {   // avg_probs columns (e bf16 * 1/Zs)
        float p0=0.f,p1=0.f;
        #pragma unroll 8
        for(int r=0;r<64;r++){
            float zi=sZs[r];
            p0=fmaf(__bfloat162float(*(const __nv_bfloat16*)(sm+r*1040+t*2)),zi,p0);
            p1=fmaf(__bfloat162float(*(const __nv_bfloat16*)(sm+r*1040+(t+256)*2)),zi,p1);
        }
        atomicAdd(&g_avg[t],p0); atomicAdd(&g_avg[t+256],p1);
    }
    __syncthreads();                                      // e dead

    // -------- GEMM2: zq[64][256] = eg @ cbn, pipelined --------
    stage_b2(smb,t,0,g_c2h,0);     CPA_COMMIT();
    stage_b2(smb,t,0,g_c2l,32768); CPA_COMMIT();
    CPA_WAIT1(); __syncthreads();

    float a2[2][8][4];
    #pragma unroll
    for(int a=0;a<2;a++)
        #pragma unroll
        for(int b=0;b<8;b++)
            #pragma unroll
            for(int c=0;c<4;c++) a2[a][b][c]=0.f;

    for(int kc=0;kc<8;kc++){
        #pragma unroll
        for(int ks=0;ks<4;ks++){
            int ggE=kc*8+2*ks+gpl, ggB=2*ks+gpl;
            uint32_t eh[2][4], el[2][4];
            #pragma unroll
            for(int mt=0;mt<2;mt++){
                int rr=mg*32+mt*16+rro;
                uint32_t ad=smb + RBOFF + rr*1024 + ((((ggE&56)|((ggE^rr)&7)))<<4);
                ldsm4(eh[mt],ad); ldsm4(el[mt],ad+65536);
            }
            #pragma unroll
            for(int nt2=0;nt2<4;nt2++){
                int rrB=ns*64+nt2*16+rro;
                uint32_t bd=smb + rrB*128 + ((ggB^(rrB&7))<<4);
                uint32_t bh[4];
                ldsm4(bh,bd);
                #pragma unroll
                for(int mt=0;mt<2;mt++){
                    mma_bf(a2[mt][2*nt2],   eh[mt], bh[0], bh[2]);
                    mma_bf(a2[mt][2*nt2+1], eh[mt], bh[1], bh[3]);
                    mma_bf(a2[mt][2*nt2],   el[mt], bh[0], bh[2]);
                    mma_bf(a2[mt][2*nt2+1], el[mt], bh[1], bh[3]);
                }
            }
        }
        __syncthreads();
        if(kc<7){ stage_b2(smb,t,kc+1,g_c2h,0); CPA_COMMIT(); CPA_WAIT1(); }
        else    { CPA_WAIT0(); }
        __syncthreads();
        #pragma unroll
        for(int ks=0;ks<4;ks++){
            int ggE=kc*8+2*ks+gpl, ggB=2*ks+gpl;
            uint32_t eh[2][4];
            #pragma unroll
            for(int mt=0;mt<2;mt++){
                int rr=mg*32+mt*16+rro;
                uint32_t ad=smb + RBOFF + rr*1024 + ((((ggE&56)|((ggE^rr)&7)))<<4);
                ldsm4(eh[mt],ad);
            }
            #pragma unroll
            for(int nt2=0;nt2<4;nt2++){
                int rrB=ns*64+nt2*16+rro;
                uint32_t bd=smb + 32768 + rrB*128 + ((ggB^(rrB&7))<<4);
                uint32_t bl[4];
                ldsm4(bl,bd);
                #pragma unroll
                for(int mt=0;mt<2;mt++){
                    mma_bf(a2[mt][2*nt2],   eh[mt], bl[0], bl[2]);
                    mma_bf(a2[mt][2*nt2+1], eh[mt], bl[1], bl[3]);
                }
            }
        }
        __syncthreads();
        if(kc<7){ stage_b2(smb,t,kc+1,g_c2l,32768); CPA_COMMIT(); CPA_WAIT1(); __syncthreads(); }
    }

    // -------- epilogue: scale, transpose, coalesced store + kldc --------
    float* sT=(float*)sm;   // [256 d][66]
    #pragma unroll
    for(int mt=0;mt<2;mt++){
        int r0=mg*32+mt*16+g, r1=r0+8;
        float zi0=sZ2[r0], zi1=sZ2[r1];
        #pragma unroll
        for(int nt=0;nt<8;nt++){
            int d0=ns*64+nt*8+2*tq;
            float* dd=a2[mt][nt];
            sT[d0*66+r0]=dd[0]*zi0; sT[(d0+1)*66+r0]=dd[1]*zi0;
            sT[d0*66+r1]=dd[2]*zi1; sT[(d0+1)*66+r1]=dd[3]*zi1;
        }
    }
    __syncthreads();
    size_t base=bb*262144 + (size_t)wh0;
    float kcc=0.f;
    #pragma unroll
    for(int i=0;i<64;i++){
        int q=t+(i<<8); int d=q>>6, r=q&63;
        float v=sT[d*66+r];
        size_t gi=base+(size_t)d*1024+r;
        float zv=z[gi];
        out[gi]=v;
        kcc=fmaf(zv,zv-v,kcc);
    }
    #pragma unroll
    for(int o=16;o;o>>=1) kcc+=__shfl_xor_sync(0xffffffffu,kcc,o);
    if(lane==0) sRed[w]=kcc;
    __syncthreads();
    if(t==0){
        float s=0.f;
        #pragma unroll
        for(int i=0;i<8;i++) s+=sRed[i];
        atomicAdd(&g_kldc,s);
    }
}

__global__ void k_fin(const float* __restrict__ kappa, float* __restrict__ out, int out_size){
    int t=threadIdx.x;
    float a=g_avg[t]*(1.f/(float)NR);
    a=fmaxf(a,1e-10f);
    float term=a*logf(a+1e-10f);
    #pragma unroll
    for(int o=16;o;o>>=1) term+=__shfl_xor_sync(0xffffffffu,term,o);
    __shared__ float ws[16];
    if((t&31)==0) ws[t>>5]=term;
    __syncthreads();
    if(t==0){
        float s=0.f;
        #pragma unroll
        for(int i=0;i<16;i++) s+=ws[i];
        float kq=fminf(fmaxf(kappa[0],1e-5f),1e5f);
        float loss=(g_kldd+g_kldc*kq)*(1.f/32.f);
        if(out_size>=8388609) out[8388608]=loss;
        if(out_size>=8388610) out[8388609]=expf(-s);
    }
}

extern "C" void kernel_launch(void* const* d_in, const int* in_sizes, int n_in,
                              void* d_out, int out_size){
    const float* z=(const float*)d_in[0];
    const float* kappa=(const float*)d_in[1];
    const float* cb=(const float*)d_in[2];
    const float* gu=(const float*)d_in[3];
    float* out=(float*)d_out;
    cudaFuncSetAttribute(k_main, cudaFuncAttributeMaxDynamicSharedMemorySize, SMTOT);
    k_zero<<<1,512>>>();
    k_norm<<<512,256>>>(cb,kappa);
    k_c2<<<256,256>>>();
    k_main<<<512,256,SMTOT>>>(gu,z,out);
    k_fin<<<1,512>>>(kappa,out,out_size);
}

// round 11
// speedup vs baseline: 2.2930x; 1.0703x over previous
#include <cuda_runtime.h>
#include <cuda_bf16.h>
#include <cstdint>
#include <math.h>

#define KD 512
#define DZ 256
#define NR 32768

// smem map (bytes): RA [0,69632)  RB [69632,200704)  MISC [200704,203552)
#define RBOFF 69632
#define MISCOFF 200704
#define SMTOT 203552

__device__ __forceinline__ uint32_t s2u(const void* p){
    uint32_t a;
    asm("{ .reg .u64 t; cvta.to.shared.u64 t,%1; cvt.u32.u64 %0,t; }" : "=r"(a) : "l"(p));
    return a;
}
__device__ __forceinline__ void ldsm4(uint32_t r[4], uint32_t a){
    asm volatile("ldmatrix.sync.aligned.m8n8.x4.shared.b16 {%0,%1,%2,%3}, [%4];"
        : "=r"(r[0]),"=r"(r[1]),"=r"(r[2]),"=r"(r[3]) : "r"(a));
}
__device__ __forceinline__ void mma_bf(float d[4], const uint32_t a[4], uint32_t b0, uint32_t b1){
    asm volatile("mma.sync.aligned.m16n8k16.row.col.f32.bf16.bf16.f32 "
        "{%0,%1,%2,%3},{%4,%5,%6,%7},{%8,%9},{%0,%1,%2,%3};"
        : "+f"(d[0]),"+f"(d[1]),"+f"(d[2]),"+f"(d[3])
        : "r"(a[0]),"r"(a[1]),"r"(a[2]),"r"(a[3]),"r"(b0),"r"(b1));
}
__device__ __forceinline__ void cpa16(uint32_t dst, const void* src){
    asm volatile("cp.async.cg.shared.global [%0], [%1], 16;" :: "r"(dst), "l"(src));
}
#define CPA_COMMIT() asm volatile("cp.async.commit_group;" ::: "memory")
#define CPA_WAIT0()  asm volatile("cp.async.wait_group 0;" ::: "memory")
#define CPA_WAIT1()  asm volatile("cp.async.wait_group 1;" ::: "memory")

__device__ __forceinline__ uint32_t packpair(float lo, float hi){
    uint32_t r; asm("cvt.rn.bf16x2.f32 %0, %1, %2;" : "=r"(r) : "f"(hi), "f"(lo)); return r;
}
__device__ __forceinline__ float lof(float x){
    return x - __bfloat162float(__float2bfloat16(x));
}

__device__ uint32_t g_c1h[KD*128];    // kq*cbn [n=512][kpair=128]
__device__ uint32_t g_c1l[KD*128];
__device__ uint32_t g_c2h[DZ*256];    // cbn^T  [d=256][jpair=256]
__device__ uint32_t g_c2l[DZ*256];
__device__ float    g_cbn[KD*DZ];
__device__ float    g_avg[KD];
__device__ float    g_kldd, g_kldc;

__global__ void k_zero(){
    int t=threadIdx.x;
    if (t<KD) g_avg[t]=0.f;
    if (t==0){ g_kldd=0.f; g_kldc=0.f; }
}

__global__ void k_norm(const float* __restrict__ cb, const float* __restrict__ kappa){
    __shared__ float rowb[256];
    __shared__ float ws[8];
    int j=blockIdx.x, t=threadIdx.x;
    float c=cb[j*DZ+t], s=c*c;
    #pragma unroll
    for(int o=16;o;o>>=1) s += __shfl_xor_sync(0xffffffffu,s,o);
    if((t&31)==0) ws[t>>5]=s;
    __syncthreads();
    float tot=0.f;
    #pragma unroll
    for(int i=0;i<8;i++) tot+=ws[i];
    float cn=c*(1.f/sqrtf(tot));
    g_cbn[j*DZ+t]=cn;
    float kq=fminf(fmaxf(kappa[0],1e-5f),1e5f);
    rowb[t]=cn*kq;
    __syncthreads();
    if(t<128){
        float a=rowb[2*t], b=rowb[2*t+1];
        g_c1h[j*128+t]=packpair(a,b);
        g_c1l[j*128+t]=packpair(lof(a),lof(b));
    }
}

__global__ void k_c2(){
    int d=blockIdx.x, t=threadIdx.x;   // t = jpair
    float a=g_cbn[(2*t)*DZ+d], b=g_cbn[(2*t+1)*DZ+d];
    g_c2h[d*256+t]=packpair(a,b);
    g_c2l[d*256+t]=packpair(lof(a),lof(b));
}

// ---- staging helpers (cp.async, one buffer each; 512 threads) ----
__device__ __forceinline__ void stage_b1(uint32_t smb, int t, int kc, const uint32_t* src, uint32_t dstoff){
    #pragma unroll
    for(int i=0;i<8;i++){
        int q=t+(i<<9); int n=q>>3, gr=q&7;
        cpa16(smb + dstoff + n*128 + ((gr^(n&7))<<4),
              (const char*)src + (size_t)(n*32 + kc*8 + gr)*16);
    }
}
__device__ __forceinline__ void stage_b2(uint32_t smb, int t, int kc, const uint32_t* src, uint32_t dstoff){
    #pragma unroll
    for(int i=0;i<4;i++){
        int q=t+(i<<9); int dd=q>>3, gr=q&7;
        cpa16(smb + dstoff + dd*128 + ((gr^(dd&7))<<4),
              (const char*)src + (size_t)(dd*64 + kc*8 + gr)*16);
    }
}

__global__ __launch_bounds__(512,1)
void k_main(const float* __restrict__ gu, const float* __restrict__ z,
            float* __restrict__ out){
    extern __shared__ char sm[];
    const uint32_t smb=s2u(sm);
    float* MISC=(float*)(sm+MISCOFF);
    float* sZs=MISC; float* sSs=MISC+64; float* sZ2=MISC+128;
    float* sRed=MISC+192;
    const int t=threadIdx.x, lane=t&31, w=t>>5;     // 16 warps
    const int mg=w&1, ns=w>>1;                      // mg 0/1, ns 0..7
    const int g=lane>>2, tq=lane&3;
    const int R0=blockIdx.x<<6;
    if(t<64){ sZs[t]=0.f; sSs[t]=0.f; sZ2[t]=0.f; }

    const size_t bb=(size_t)(R0>>10);
    const int wh0=R0&1023;
    const float* zb = z + bb*262144 + wh0;

    // ---- G0: z slab -> sZ (RB upper, 64KB); G1: bh(0) -> RB lower ----
    #pragma unroll
    for(int i=0;i<8;i++){
        int q=t+(i<<9); int d=q>>4, j4=q&15;
        cpa16(smb + RBOFF + 65536 + (q<<4),
              (const char*)zb + ((size_t)d*4096 + j4*16));
    }
    CPA_COMMIT();
    stage_b1(smb,t,0,g_c1h,RBOFF);       CPA_COMMIT();   // bh(0)
    CPA_WAIT1();  __syncthreads();                        // z ready

    // ---- pack A tiles (hi at RA[0,32K), lo at RA[32K,64K)) ----
    {
        const float* sZf=(const float*)(sm + RBOFF + 65536);
        #pragma unroll
        for(int i=0;i<4;i++){
            int m=(t&31)+((i&1)<<5);
            int gr=(t>>5)+((i>>1)<<4);
            float v[8];
            #pragma unroll
            for(int c=0;c<8;c++) v[c]=sZf[(8*gr+c)*64 + m];
            int swz=(gr&24)|((gr^m)&7);
            uint32_t off=(uint32_t)(m*512 + (swz<<4));
            *(uint4*)(sm + off)=make_uint4(packpair(v[0],v[1]),packpair(v[2],v[3]),
                                           packpair(v[4],v[5]),packpair(v[6],v[7]));
            *(uint4*)(sm + 32768 + off)=make_uint4(packpair(lof(v[0]),lof(v[1])),packpair(lof(v[2]),lof(v[3])),
                                                   packpair(lof(v[4]),lof(v[5])),packpair(lof(v[6]),lof(v[7])));
        }
    }
    __syncthreads();                                      // sZ dead
    stage_b1(smb,t,0,g_c1l,RBOFF+65536); CPA_COMMIT();    // bl(0) overwrites sZ
    CPA_WAIT1(); __syncthreads();                         // bh(0) ready

    const int sub=lane>>3, rro=(lane&7)+((sub&1)<<3), gpl=sub>>1;

    float a1[2][8][4];
    #pragma unroll
    for(int a=0;a<2;a++)
        #pragma unroll
        for(int b=0;b<8;b++)
            #pragma unroll
            for(int c=0;c<4;c++) a1[a][b][c]=0.f;

    // -------- GEMM1: logits[64][512], warp tile 32m x 64n --------
    for(int kc=0;kc<4;kc++){
        // p1+p2: (ah+al) x bh   (bl(kc) in flight)
        #pragma unroll
        for(int ks=0;ks<4;ks++){
            int ggA=kc*8+2*ks+gpl, ggB=2*ks+gpl;
            uint32_t ah[2][4], al[2][4];
            #pragma unroll
            for(int mt=0;mt<2;mt++){
                int rr=mg*32+mt*16+rro;
                uint32_t ad=smb + rr*512 + ((((ggA&24)|((ggA^rr)&7)))<<4);
                ldsm4(ah[mt],ad); ldsm4(al[mt],ad+32768);
            }
            #pragma unroll
            for(int nt2=0;nt2<4;nt2++){
                int rrB=ns*64+nt2*16+rro;
                uint32_t bd=smb + RBOFF + rrB*128 + ((ggB^(rrB&7))<<4);
                uint32_t bh[4];
                ldsm4(bh,bd);
                #pragma unroll
                for(int mt=0;mt<2;mt++){
                    mma_bf(a1[mt][2*nt2],   ah[mt], bh[0], bh[2]);
                    mma_bf(a1[mt][2*nt2+1], ah[mt], bh[1], bh[3]);
                    mma_bf(a1[mt][2*nt2],   al[mt], bh[0], bh[2]);
                    mma_bf(a1[mt][2*nt2+1], al[mt], bh[1], bh[3]);
                }
            }
        }
        __syncthreads();
        if(kc<3){ stage_b1(smb,t,kc+1,g_c1h,RBOFF); CPA_COMMIT(); CPA_WAIT1(); }
        else    { CPA_WAIT0(); }
        __syncthreads();                                  // bl(kc) ready
        // p3: ah x bl   (bh(kc+1) in flight)
        #pragma unroll
        for(int ks=0;ks<4;ks++){
            int ggA=kc*8+2*ks+gpl, ggB=2*ks+gpl;
            uint32_t ah[2][4];
            #pragma unroll
            for(int mt=0;mt<2;mt++){
                int rr=mg*32+mt*16+rro;
                uint32_t ad=smb + rr*512 + ((((ggA&24)|((ggA^rr)&7)))<<4);
                ldsm4(ah[mt],ad);
            }
            #pragma unroll
            for(int nt2=0;nt2<4;nt2++){
                int rrB=ns*64+nt2*16+rro;
                uint32_t bd=smb + RBOFF + 65536 + rrB*128 + ((ggB^(rrB&7))<<4);
                uint32_t bl[4];
                ldsm4(bl,bd);
                #pragma unroll
                for(int mt=0;mt<2;mt++){
                    mma_bf(a1[mt][2*nt2],   ah[mt], bl[0], bl[2]);
                    mma_bf(a1[mt][2*nt2+1], ah[mt], bl[1], bl[3]);
                }
            }
        }
        __syncthreads();
        if(kc<3){ stage_b1(smb,t,kc+1,g_c1l,RBOFF+65536); CPA_COMMIT(); CPA_WAIT1(); __syncthreads(); }
    }

    // -------- softmax + gumbel (from regs); e->RA bf16, eg->RB bf16 hi/lo --------
    #pragma unroll
    for(int mt=0;mt<2;mt++){
        int r0=mg*32+mt*16+g, r1=r0+8;
        const float* gur0 = gu + (size_t)(R0+r0)*512 + ns*64 + 2*tq;
        const float* gur1 = gu + (size_t)(R0+r1)*512 + ns*64 + 2*tq;
        float2 nu0=*(const float2*)gur0, nu1=*(const float2*)gur1;
        float Zs0=0,Ss0=0,Q0=0, Zs1=0,Ss1=0,Q1=0;
        #pragma unroll
        for(int nt=0;nt<8;nt++){
            float2 u0=nu0, u1=nu1;
            if(nt<7){ nu0=*(const float2*)(gur0+(nt+1)*8); nu1=*(const float2*)(gur1+(nt+1)*8); }
            int col=ns*64+nt*8+2*tq;
            float* dd=a1[mt][nt];
            float e0=__expf(dd[0]), e1=__expf(dd[1]);
            float e2=__expf(dd[2]), e3=__expf(dd[3]);
            Zs0+=e0+e1; Ss0+=e0*dd[0]+e1*dd[1];
            Zs1+=e2+e3; Ss1+=e2*dd[2]+e3*dd[3];
            *(uint32_t*)(sm + r0*1040 + col*2)=packpair(e0,e1);
            *(uint32_t*)(sm + r1*1040 + col*2)=packpair(e2,e3);
            float w0=-__logf(u0.x+1e-10f), w1=-__logf(u0.y+1e-10f);
            float w2=-__logf(u1.x+1e-10f), w3=-__logf(u1.y+1e-10f);
            float v0=__fdividef(e0,w0+1e-10f), v1=__fdividef(e1,w1+1e-10f);
            float v2=__fdividef(e2,w2+1e-10f), v3=__fdividef(e3,w3+1e-10f);
            float q0=v0*v0,q1=v1*v1,q2=v2*v2,q3=v3*v3;
            Q0+=q0+q1; Q1+=q2+q3;
            int gf=col>>3; int swz=(gf&56)|((gf^(r0&7))&7);
            uint32_t off=(uint32_t)(swz<<4)+4*tq;
            *(uint32_t*)(sm + RBOFF + r0*1024 + off)=packpair(q0,q1);
            *(uint32_t*)(sm + RBOFF + 65536 + r0*1024 + off)=packpair(lof(q0),lof(q1));
            *(uint32_t*)(sm + RBOFF + r1*1024 + off)=packpair(q2,q3);
            *(uint32_t*)(sm + RBOFF + 65536 + r1*1024 + off)=packpair(lof(q2),lof(q3));
        }
        atomicAdd(&sZs[r0],Zs0); atomicAdd(&sSs[r0],Ss0); atomicAdd(&sZ2[r0],Q0);
        atomicAdd(&sZs[r1],Zs1); atomicAdd(&sSs[r1],Ss1); atomicAdd(&sZ2[r1],Q1);
    }
    __syncthreads();
    if(t<64){
        float zs=sZs[t], inv=1.f/zs;
        float kd=sSs[t]*inv-__logf(zs);
        sZs[t]=inv;
        sZ2[t]=1.f/sZ2[t];
        #pragma unroll
        for(int o=16;o;o>>=1) kd+=__shfl_xor_sync(0xffffffffu,kd,o);
        if(lane==0) atomicAdd(&g_kldd,kd);
    }
    __syncthreads();
    {   // avg_probs: one column per thread (t in [0,512))
        float p0=0.f;
        #pragma unroll 8
        for(int r=0;r<64;r++){
            p0=fmaf(__bfloat162float(*(const __nv_bfloat16*)(sm+r*1040+t*2)),sZs[r],p0);
        }
        atomicAdd(&g_avg[t],p0);
    }
    __syncthreads();                                      // e dead

    // -------- GEMM2: zq[64][256] = eg @ cbn, warp tile 32m x 32n --------
    stage_b2(smb,t,0,g_c2h,0);     CPA_COMMIT();
    stage_b2(smb,t,0,g_c2l,32768); CPA_COMMIT();
    CPA_WAIT1(); __syncthreads();

    float a2[2][4][4];
    #pragma unroll
    for(int a=0;a<2;a++)
        #pragma unroll
        for(int b=0;b<4;b++)
            #pragma unroll
            for(int c=0;c<4;c++) a2[a][b][c]=0.f;

    for(int kc=0;kc<8;kc++){
        #pragma unroll
        for(int ks=0;ks<4;ks++){
            int ggE=kc*8+2*ks+gpl, ggB=2*ks+gpl;
            uint32_t eh[2][4], el[2][4];
            #pragma unroll
            for(int mt=0;mt<2;mt++){
                int rr=mg*32+mt*16+rro;
                uint32_t ad=smb + RBOFF + rr*1024 + ((((ggE&56)|((ggE^rr)&7)))<<4);
                ldsm4(eh[mt],ad); ldsm4(el[mt],ad+65536);
            }
            #pragma unroll
            for(int nt2=0;nt2<2;nt2++){
                int rrB=ns*32+nt2*16+rro;
                uint32_t bd=smb + rrB*128 + ((ggB^(rrB&7))<<4);
                uint32_t bh[4];
                ldsm4(bh,bd);
                #pragma unroll
                for(int mt=0;mt<2;mt++){
                    mma_bf(a2[mt][2*nt2],   eh[mt], bh[0], bh[2]);
                    mma_bf(a2[mt][2*nt2+1], eh[mt], bh[1], bh[3]);
                    mma_bf(a2[mt][2*nt2],   el[mt], bh[0], bh[2]);
                    mma_bf(a2[mt][2*nt2+1], el[mt], bh[1], bh[3]);
                }
            }
        }
        __syncthreads();
        if(kc<7){ stage_b2(smb,t,kc+1,g_c2h,0); CPA_COMMIT(); CPA_WAIT1(); }
        else    { CPA_WAIT0(); }
        __syncthreads();
        #pragma unroll
        for(int ks=0;ks<4;ks++){
            int ggE=kc*8+2*ks+gpl, ggB=2*ks+gpl;
            uint32_t eh[2][4];
            #pragma unroll
            for(int mt=0;mt<2;mt++){
                int rr=mg*32+mt*16+rro;
                uint32_t ad=smb + RBOFF + rr*1024 + ((((ggE&56)|((ggE^rr)&7)))<<4);
                ldsm4(eh[mt],ad);
            }
            #pragma unroll
            for(int nt2=0;nt2<2;nt2++){
                int rrB=ns*32+nt2*16+rro;
                uint32_t bd=smb + 32768 + rrB*128 + ((ggB^(rrB&7))<<4);
                uint32_t bl[4];
                ldsm4(bl,bd);
                #pragma unroll
                for(int mt=0;mt<2;mt++){
                    mma_bf(a2[mt][2*nt2],   eh[mt], bl[0], bl[2]);
                    mma_bf(a2[mt][2*nt2+1], eh[mt], bl[1], bl[3]);
                }
            }
        }
        __syncthreads();
        if(kc<7){ stage_b2(smb,t,kc+1,g_c2l,32768); CPA_COMMIT(); CPA_WAIT1(); __syncthreads(); }
    }

    // -------- epilogue: scale, transpose, coalesced store + kldc --------
    float* sT=(float*)sm;   // [256 d][66]
    #pragma unroll
    for(int mt=0;mt<2;mt++){
        int r0=mg*32+mt*16+g, r1=r0+8;
        float zi0=sZ2[r0], zi1=sZ2[r1];
        #pragma unroll
        for(int nt=0;nt<4;nt++){
            int d0=ns*32+nt*8+2*tq;
            float* dd=a2[mt][nt];
            sT[d0*66+r0]=dd[0]*zi0; sT[(d0+1)*66+r0]=dd[1]*zi0;
            sT[d0*66+r1]=dd[2]*zi1; sT[(d0+1)*66+r1]=dd[3]*zi1;
        }
    }
    __syncthreads();
    size_t base=bb*262144 + (size_t)wh0;
    float kcc=0.f;
    #pragma unroll
    for(int i=0;i<32;i++){
        int q=t+(i<<9); int d=q>>6, r=q&63;
        float v=sT[d*66+r];
        size_t gi=base+(size_t)d*1024+r;
        float zv=z[gi];
        out[gi]=v;
        kcc=fmaf(zv,zv-v,kcc);
    }
    #pragma unroll
    for(int o=16;o;o>>=1) kcc+=__shfl_xor_sync(0xffffffffu,kcc,o);
    if(lane==0) sRed[w]=kcc;
    __syncthreads();
    if(t==0){
        float s=0.f;
        #pragma unroll
        for(int i=0;i<16;i++) s+=sRed[i];
        atomicAdd(&g_kldc,s);
    }
}

__global__ void k_fin(const float* __restrict__ kappa, float* __restrict__ out, int out_size){
    int t=threadIdx.x;
    float a=g_avg[t]*(1.f/(float)NR);
    a=fmaxf(a,1e-10f);
    float term=a*logf(a+1e-10f);
    #pragma unroll
    for(int o=16;o;o>>=1) term+=__shfl_xor_sync(0xffffffffu,term,o);
    __shared__ float ws[16];
    if((t&31)==0) ws[t>>5]=term;
    __syncthreads();
    if(t==0){
        float s=0.f;
        #pragma unroll
        for(int i=0;i<16;i++) s+=ws[i];
        float kq=fminf(fmaxf(kappa[0],1e-5f),1e5f);
        float loss=(g_kldd+g_kldc*kq)*(1.f/32.f);
        if(out_size>=8388609) out[8388608]=loss;
        if(out_size>=8388610) out[8388609]=expf(-s);
    }
}

extern "C" void kernel_launch(void* const* d_in, const int* in_sizes, int n_in,
                              void* d_out, int out_size){
    const float* z=(const float*)d_in[0];
    const float* kappa=(const float*)d_in[1];
    const float* cb=(const float*)d_in[2];
    const float* gu=(const float*)d_in[3];
    float* out=(float*)d_out;
    cudaFuncSetAttribute(k_main, cudaFuncAttributeMaxDynamicSharedMemorySize, SMTOT);
    k_zero<<<1,512>>>();
    k_norm<<<512,256>>>(cb,kappa);
    k_c2<<<256,256>>>();
    k_main<<<512,512,SMTOT>>>(gu,z,out);
    k_fin<<<1,512>>>(kappa,out,out_size);
}